// round 2
// baseline (speedup 1.0000x reference)
#include <cuda_runtime.h>
#include <math.h>
#include <stdint.h>

// Problem constants (T=1024, B=32, I=512, H=512)
#define T_STEPS 1024
#define BATCH   32
#define IDIM    512
#define HDIM    512
#define GDIM    2048   // 4*H, torch gate order (i, f, g, o)
#define NBLK    128    // persistent blocks (<= 148 SMs, co-resident)

// Scratch: precomputed input projection Gx[t][b][4H] = x_t @ Wx^T + b  (256 MB)
__device__ float g_Gx[(size_t)T_STEPS * BATCH * GDIM];

// Grid barrier state
__device__ unsigned g_count = 0;
__device__ volatile unsigned g_gen = 0;

// ---------------------------------------------------------------------------
// Phase 1: Gx = X @ Wx^T + b.  X:[M,K] row-major, Wx:[N,K] row-major.
// Classic 128x128x8 SGEMM, 256 threads, 8x8 per-thread tile.
// ---------------------------------------------------------------------------
__global__ __launch_bounds__(256) void gemm_xw(
    const float* __restrict__ A,
    const float* __restrict__ W,
    const float* __restrict__ bias)
{
    const int K = IDIM, N = GDIM;
    __shared__ float As[8][128];
    __shared__ float Bs[8][128];

    int tid  = threadIdx.x;
    int tx   = tid & 15;
    int ty   = tid >> 4;
    int lrow = tid >> 1;
    int lk4  = (tid & 1) << 2;

    const float* Ag = A + (size_t)(blockIdx.y * 128 + lrow) * K + lk4;
    const float* Wg = W + (size_t)(blockIdx.x * 128 + lrow) * K + lk4;

    float acc[8][8];
#pragma unroll
    for (int i = 0; i < 8; i++)
#pragma unroll
        for (int j = 0; j < 8; j++) acc[i][j] = 0.f;

    for (int k0 = 0; k0 < K; k0 += 8) {
        float4 a = *(const float4*)(Ag + k0);
        float4 w = *(const float4*)(Wg + k0);
        As[lk4 + 0][lrow] = a.x; As[lk4 + 1][lrow] = a.y;
        As[lk4 + 2][lrow] = a.z; As[lk4 + 3][lrow] = a.w;
        Bs[lk4 + 0][lrow] = w.x; Bs[lk4 + 1][lrow] = w.y;
        Bs[lk4 + 2][lrow] = w.z; Bs[lk4 + 3][lrow] = w.w;
        __syncthreads();
#pragma unroll
        for (int k = 0; k < 8; k++) {
            float ar[8], br[8];
            *(float4*)(ar)     = *(const float4*)&As[k][ty * 4];
            *(float4*)(ar + 4) = *(const float4*)&As[k][ty * 4 + 64];
            *(float4*)(br)     = *(const float4*)&Bs[k][tx * 4];
            *(float4*)(br + 4) = *(const float4*)&Bs[k][tx * 4 + 64];
#pragma unroll
            for (int i = 0; i < 8; i++)
#pragma unroll
                for (int j = 0; j < 8; j++)
                    acc[i][j] += ar[i] * br[j];
        }
        __syncthreads();
    }

#pragma unroll
    for (int i = 0; i < 8; i++) {
        int r = blockIdx.y * 128 + ((i < 4) ? (ty * 4 + i) : (64 + ty * 4 + (i - 4)));
#pragma unroll
        for (int jh = 0; jh < 2; jh++) {
            int c0 = blockIdx.x * 128 + ((jh == 0) ? (tx * 4) : (64 + tx * 4));
            float4 o;
            o.x = acc[i][jh * 4 + 0] + bias[c0 + 0];
            o.y = acc[i][jh * 4 + 1] + bias[c0 + 1];
            o.z = acc[i][jh * 4 + 2] + bias[c0 + 2];
            o.w = acc[i][jh * 4 + 3] + bias[c0 + 3];
            *(float4*)&g_Gx[(size_t)r * N + c0] = o;
        }
    }
}

// ---------------------------------------------------------------------------
// cp.async helpers (L1-bypass .cg flavor: also gives cross-SM h coherence)
// ---------------------------------------------------------------------------
__device__ __forceinline__ void cp_async16(uint32_t saddr, const void* gptr) {
    asm volatile("cp.async.cg.shared.global [%0], [%1], 16;\n"
                 :: "r"(saddr), "l"(gptr));
}
__device__ __forceinline__ void cp_commit() {
    asm volatile("cp.async.commit_group;\n");
}
__device__ __forceinline__ void cp_wait0() {
    asm volatile("cp.async.wait_group 0;\n");
}

// ---------------------------------------------------------------------------
// Persistent LSTM recurrence kernel.
// 128 blocks x 256 threads. Block bx owns h-columns j0..j0+3 (16 Wh rows).
// Thread mapping: ks = tid&15 (K-split), tn = (tid>>4)&3 (4 of 16 gate cols),
//                 tb = tid>>6 (8 of 32 batches).
// smem (dynamic, floats):
//   WH [4][16][132]  offset 0      (8448)  - Wh slice, cached once
//   HS [2][32][132]  offset 8448   (8448)  - h staging, double buffered
//   EX [16*33]       offset 16896  (528)   - gate-sum exchange
// Total 17424 floats = 69696 bytes.
// ---------------------------------------------------------------------------
#define WH_OFF 0
#define HS_OFF 8448
#define EX_OFF 16896
#define SMEM_FLOATS 17424

__device__ __forceinline__ void grid_barrier() {
    __syncthreads();
    if (threadIdx.x == 0) {
        __threadfence();
        unsigned gen = g_gen;
        if (atomicAdd(&g_count, 1) == (unsigned)(gridDim.x - 1)) {
            atomicExch(&g_count, 0);
            __threadfence();
            g_gen = gen + 1;
        } else {
            while (g_gen == gen) { }
            __threadfence();
        }
    }
    __syncthreads();
}

__global__ __launch_bounds__(256, 1) void lstm_persist(
    const float* __restrict__ h0,
    const float* __restrict__ c0,
    const float* __restrict__ Wh,
    float* __restrict__ out,    // [T][32][512]
    float* __restrict__ allh,   // [T][32][512]
    float* __restrict__ hT,     // [32][512]
    float* __restrict__ cT)     // [32][512]
{
    extern __shared__ float sm[];
    float* WHp = sm + WH_OFF;
    float* EXp = sm + EX_OFF;

    const int tid = threadIdx.x;
    const int j0  = blockIdx.x * 4;
    const int ks  = tid & 15;
    const int tn  = (tid >> 4) & 3;
    const int tb  = tid >> 6;

    uint32_t smem_base = (uint32_t)__cvta_generic_to_shared(sm);

    // --- one-time: cache Wh slice [16 rows x 512] chunked [4][16][132] ---
    for (int idx = tid; idx < 2048; idx += 256) {
        int kc = idx >> 9;
        int n  = (idx >> 5) & 15;
        int q  = idx & 31;
        int R  = ((n >> 2) << 9) + j0 + (n & 3);   // gate*512 + j
        float4 v = *(const float4*)(Wh + (size_t)R * HDIM + kc * 128 + q * 4);
        float* d = &WHp[kc * 2112 + n * 132 + q * 4];
        d[0] = v.x; d[1] = v.y; d[2] = v.z; d[3] = v.w;
    }

    // --- c state in registers (threads 0..127 own (b, jj)) ---
    int ab = tid >> 2, aj = tid & 3;
    float c_reg = 0.f;
    if (tid < 128) c_reg = c0[ab * HDIM + j0 + aj];
    __syncthreads();

    const float* hsrc = h0;

    for (int t = 0; t < T_STEPS; t++) {
        // prefetch h chunk 0 into HS buffer 0
        {
#pragma unroll
            for (int r = 0; r < 4; r++) {
                int idx = tid + r * 256;
                int b = idx >> 5, q = idx & 31;
                uint32_t sa = smem_base + (HS_OFF + b * 132 + q * 4) * 4;
                cp_async16(sa, hsrc + b * HDIM + q * 4);
            }
            cp_commit();
        }

        // prefetch this thread's Gx values (hidden under the compute loop)
        float gxv[4];
        if (tid < 128) {
            const float* gx = g_Gx + (size_t)t * BATCH * GDIM + ab * GDIM + j0 + aj;
#pragma unroll
            for (int g = 0; g < 4; g++) gxv[g] = __ldg(gx + g * HDIM);
        }

        float acc[8][4];
#pragma unroll
        for (int i = 0; i < 8; i++)
#pragma unroll
            for (int n = 0; n < 4; n++) acc[i][n] = 0.f;

#pragma unroll
        for (int kc = 0; kc < 4; kc++) {
            cp_wait0();
            __syncthreads();
            if (kc < 3) {
                int nb = (kc + 1) & 1;
                int k0 = (kc + 1) * 128;
#pragma unroll
                for (int r = 0; r < 4; r++) {
                    int idx = tid + r * 256;
                    int b = idx >> 5, q = idx & 31;
                    uint32_t sa = smem_base + (HS_OFF + nb * 4224 + b * 132 + q * 4) * 4;
                    cp_async16(sa, hsrc + b * HDIM + k0 + q * 4);
                }
                cp_commit();
            }
            const float* hb = sm + HS_OFF + (kc & 1) * 4224;
            const float* wb = WHp + kc * 2112;
#pragma unroll
            for (int m = 0; m < 8; m++) {
                int k = ks + (m << 4);
                float wv[4];
#pragma unroll
                for (int n = 0; n < 4; n++) wv[n] = wb[(tn * 4 + n) * 132 + k];
#pragma unroll
                for (int i = 0; i < 8; i++) {
                    float hv = hb[(tb * 8 + i) * 132 + k];
#pragma unroll
                    for (int n = 0; n < 4; n++) acc[i][n] += hv * wv[n];
                }
            }
        }

        // K-split reduction over 16 adjacent lanes via shuffles
#pragma unroll
        for (int i = 0; i < 8; i++)
#pragma unroll
            for (int n = 0; n < 4; n++) {
                float v = acc[i][n];
                v += __shfl_down_sync(0xffffffffu, v, 8, 16);
                v += __shfl_down_sync(0xffffffffu, v, 4, 16);
                v += __shfl_down_sync(0xffffffffu, v, 2, 16);
                v += __shfl_down_sync(0xffffffffu, v, 1, 16);
                if (ks == 0) EXp[(tn * 4 + n) * 33 + (tb * 8 + i)] = v;
            }
        __syncthreads();

        // activations for (b=ab, j=j0+aj) on threads 0..127
        if (tid < 128) {
            float g4[4];
#pragma unroll
            for (int g = 0; g < 4; g++)
                g4[g] = EXp[(g * 4 + aj) * 33 + ab] + gxv[g];
            float ig = 1.f / (1.f + __expf(-g4[0]));
            float fg = 1.f / (1.f + __expf(-g4[1]));
            float gg = tanhf(g4[2]);
            float og = 1.f / (1.f + __expf(-g4[3]));
            c_reg = fg * c_reg + ig * gg;
            float hn = og * tanhf(c_reg);
            int off = ab * HDIM + j0 + aj;
            out [(size_t)t * BATCH * HDIM + off] = hn;
            allh[(size_t)t * BATCH * HDIM + off] = hn;
            if (t == T_STEPS - 1) {
                hT[off] = hn;
                cT[off] = c_reg;
            }
        }

        grid_barrier();
        hsrc = out + (size_t)t * BATCH * HDIM;
    }
}

// ---------------------------------------------------------------------------
// Inputs (metadata order): x[T,B,I], h0[1,B,H], c0[1,B,H], Wx[4H,I], Wh[4H,H], b[4H]
// Output: concat(output[T,B,H], h_T[1,B,H], c_T[1,B,H], all_hidden[T,B,H])
// ---------------------------------------------------------------------------
extern "C" void kernel_launch(void* const* d_in, const int* in_sizes, int n_in,
                              void* d_out, int out_size)
{
    const float* x    = (const float*)d_in[0];
    const float* h0   = (const float*)d_in[1];
    const float* c0   = (const float*)d_in[2];
    const float* Wx   = (const float*)d_in[3];
    const float* Wh   = (const float*)d_in[4];
    const float* bias = (const float*)d_in[5];

    float* out  = (float*)d_out;
    float* hT   = out + (size_t)T_STEPS * BATCH * HDIM;
    float* cT   = hT + BATCH * HDIM;
    float* allh = cT + BATCH * HDIM;

    // Phase 1: input projection for all timesteps (one node)
    dim3 ggrid(GDIM / 128, (T_STEPS * BATCH) / 128);
    gemm_xw<<<ggrid, 256>>>(x, Wx, bias);

    // Phase 2: entire recurrence in one persistent kernel (one node)
    cudaFuncSetAttribute(lstm_persist,
                         cudaFuncAttributeMaxDynamicSharedMemorySize,
                         SMEM_FLOATS * (int)sizeof(float));
    lstm_persist<<<NBLK, 256, SMEM_FLOATS * sizeof(float)>>>(
        h0, c0, Wh, out, allh, hT, cT);
}

// round 3
// speedup vs baseline: 1.1747x; 1.1747x over previous
#include <cuda_runtime.h>
#include <math.h>
#include <stdint.h>

// Problem constants (T=1024, B=32, I=512, H=512)
#define T_STEPS 1024
#define BATCH   32
#define IDIM    512
#define HDIM    512
#define GDIM    2048   // 4*H, torch gate order (i, f, g, o)
#define NBLK    128    // persistent blocks (<= 148 SMs, co-resident)

typedef unsigned long long ULL;

// Scratch: precomputed input projection Gx[t][b][4H] = x_t @ Wx^T + b  (256 MB)
__device__ float g_Gx[(size_t)T_STEPS * BATCH * GDIM];

// Per-chunk producer counters, double-buffered by step parity. Monotonic within
// a launch; reset to 0 at launch end (behind the terminal grid barrier).
__device__ unsigned g_cnt[2][4];

// Terminal grid barrier state (replay-safe: count returns to 0, gen monotonic)
__device__ unsigned g_count = 0;
__device__ volatile unsigned g_gen = 0;

// ---------------------------------------------------------------------------
// f32x2 packed-math helpers (sm_100+; ptxas never emits these from C++)
// ---------------------------------------------------------------------------
__device__ __forceinline__ void ffma2(ULL& acc, ULL a, ULL b) {
    asm("fma.rn.f32x2 %0, %1, %2, %0;" : "+l"(acc) : "l"(a), "l"(b));
}
__device__ __forceinline__ ULL fadd2(ULL a, ULL b) {
    ULL r; asm("add.rn.f32x2 %0, %1, %2;" : "=l"(r) : "l"(a), "l"(b)); return r;
}
__device__ __forceinline__ ULL pack2(float lo, float hi) {
    ULL r; asm("mov.b64 %0, {%1, %2};" : "=l"(r) : "f"(lo), "f"(hi)); return r;
}
__device__ __forceinline__ ULL splat2(float x) {
    ULL r; asm("mov.b64 %0, {%1, %1};" : "=l"(r) : "f"(x)); return r;
}
__device__ __forceinline__ void unpack2(ULL v, float& lo, float& hi) {
    asm("mov.b64 {%0, %1}, %2;" : "=f"(lo), "=f"(hi) : "l"(v));
}

// ---------------------------------------------------------------------------
// cp.async helpers (.cg = L1-bypass: gives cross-SM h coherence via L2)
// ---------------------------------------------------------------------------
__device__ __forceinline__ void cp_async16(uint32_t saddr, const void* gptr) {
    asm volatile("cp.async.cg.shared.global [%0], [%1], 16;\n"
                 :: "r"(saddr), "l"(gptr));
}
__device__ __forceinline__ void cp_commit() {
    asm volatile("cp.async.commit_group;\n");
}
template<int N> __device__ __forceinline__ void cp_wait() {
    asm volatile("cp.async.wait_group %0;\n" :: "n"(N));
}

__device__ __forceinline__ unsigned ld_acquire(const unsigned* p) {
    unsigned v;
    asm volatile("ld.acquire.gpu.global.u32 %0, [%1];" : "=r"(v) : "l"(p) : "memory");
    return v;
}

// ---------------------------------------------------------------------------
// Phase 1: Gx = X @ Wx^T + b.  128x128 tile, 256 threads, 8x8/thread,
// double-buffered smem, f32x2 accumulation.  M=32768, N=2048, K=512.
// ---------------------------------------------------------------------------
__global__ __launch_bounds__(256, 2) void gemm_xw(
    const float* __restrict__ A,
    const float* __restrict__ W,
    const float* __restrict__ bias)
{
    const int K = IDIM, N = GDIM;
    __shared__ float As[2][8][128];
    __shared__ float Bs[2][8][128];

    int tid  = threadIdx.x;
    int tx   = tid & 15;
    int ty   = tid >> 4;
    int lrow = tid >> 1;
    int lk4  = (tid & 1) << 2;

    const float* Ag = A + (size_t)(blockIdx.y * 128 + lrow) * K + lk4;
    const float* Wg = W + (size_t)(blockIdx.x * 128 + lrow) * K + lk4;

    ULL acc2[4][8];
#pragma unroll
    for (int p = 0; p < 4; p++)
#pragma unroll
        for (int j = 0; j < 8; j++) acc2[p][j] = 0ull;

    // prologue: slice 0
    float4 a = *(const float4*)(Ag);
    float4 w = *(const float4*)(Wg);
    As[0][lk4 + 0][lrow] = a.x; As[0][lk4 + 1][lrow] = a.y;
    As[0][lk4 + 2][lrow] = a.z; As[0][lk4 + 3][lrow] = a.w;
    Bs[0][lk4 + 0][lrow] = w.x; Bs[0][lk4 + 1][lrow] = w.y;
    Bs[0][lk4 + 2][lrow] = w.z; Bs[0][lk4 + 3][lrow] = w.w;
    __syncthreads();

    int buf = 0;
    for (int k0 = 0; k0 < K; k0 += 8) {
        if (k0 + 8 < K) {
            a = *(const float4*)(Ag + k0 + 8);
            w = *(const float4*)(Wg + k0 + 8);
        }
#pragma unroll
        for (int k = 0; k < 8; k++) {
            float4 a0 = *(const float4*)&As[buf][k][ty * 4];
            float4 a1 = *(const float4*)&As[buf][k][ty * 4 + 64];
            float4 b0 = *(const float4*)&Bs[buf][k][tx * 4];
            float4 b1 = *(const float4*)&Bs[buf][k][tx * 4 + 64];
            ULL ap[4];
            ap[0] = pack2(a0.x, a0.y); ap[1] = pack2(a0.z, a0.w);
            ap[2] = pack2(a1.x, a1.y); ap[3] = pack2(a1.z, a1.w);
            float brf[8] = {b0.x, b0.y, b0.z, b0.w, b1.x, b1.y, b1.z, b1.w};
            ULL bp[8];
#pragma unroll
            for (int j = 0; j < 8; j++) bp[j] = splat2(brf[j]);
#pragma unroll
            for (int p = 0; p < 4; p++)
#pragma unroll
                for (int j = 0; j < 8; j++)
                    ffma2(acc2[p][j], ap[p], bp[j]);
        }
        if (k0 + 8 < K) {
            int nb = buf ^ 1;
            As[nb][lk4 + 0][lrow] = a.x; As[nb][lk4 + 1][lrow] = a.y;
            As[nb][lk4 + 2][lrow] = a.z; As[nb][lk4 + 3][lrow] = a.w;
            Bs[nb][lk4 + 0][lrow] = w.x; Bs[nb][lk4 + 1][lrow] = w.y;
            Bs[nb][lk4 + 2][lrow] = w.z; Bs[nb][lk4 + 3][lrow] = w.w;
            __syncthreads();
            buf = nb;
        }
    }

    // epilogue
#pragma unroll
    for (int i = 0; i < 8; i++) {
        int r = blockIdx.y * 128 + ((i < 4) ? (ty * 4 + i) : (64 + ty * 4 + (i - 4)));
#pragma unroll
        for (int jh = 0; jh < 2; jh++) {
            int c0 = blockIdx.x * 128 + ((jh == 0) ? (tx * 4) : (64 + tx * 4));
            float v[4];
#pragma unroll
            for (int jj = 0; jj < 4; jj++) {
                float lo, hi;
                unpack2(acc2[i >> 1][jh * 4 + jj], lo, hi);
                v[jj] = (i & 1) ? hi : lo;
            }
            float4 o;
            o.x = v[0] + bias[c0 + 0];
            o.y = v[1] + bias[c0 + 1];
            o.z = v[2] + bias[c0 + 2];
            o.w = v[3] + bias[c0 + 3];
            *(float4*)&g_Gx[(size_t)r * N + c0] = o;
        }
    }
}

// ---------------------------------------------------------------------------
// Persistent LSTM recurrence.
// 128 blocks x 256 threads. Block bx owns h-columns j0..j0+3 (16 Wh rows).
// Thread map: ks = lane (tid&31, K-split 32), tn = (tid>>5)&1 (8 of 16 gate
// cols), tb = tid>>6 (8 of 32 batches). 8x8 output tile per (tn,tb) group,
// accumulated as f32x2 pairs along the batch dim.
// smem (floats):
//   WH [4][16][132]  @0      (8448)   Wh slice, cached once
//   HS [4][32][132]  @8448   (16896)  full h staging (one step)
//   EX [16][34]      @25344  (544)    gate-sum exchange
// ---------------------------------------------------------------------------
#define WH_OFF 0
#define HS_OFF 8448
#define EX_OFF 25344
#define SMEM_FLOATS 25888

__global__ __launch_bounds__(256, 1) void lstm_persist(
    const float* __restrict__ h0,
    const float* __restrict__ c0,
    const float* __restrict__ Wh,
    float* __restrict__ out,    // [T][32][512]
    float* __restrict__ allh,   // [T][32][512]
    float* __restrict__ hT,     // [32][512]
    float* __restrict__ cT)     // [32][512]
{
    extern __shared__ float sm[];
    float* WHp = sm + WH_OFF;
    float* EXp = sm + EX_OFF;

    const int tid = threadIdx.x;
    const int j0  = blockIdx.x * 4;
    const int ks  = tid & 31;          // lane == K-split index
    const int tn  = (tid >> 5) & 1;    // gate-col half
    const int tb  = tid >> 6;          // batch quarter
    const int kc_own = blockIdx.x >> 5;

    uint32_t smem_base = (uint32_t)__cvta_generic_to_shared(sm);

    // one-time: cache Wh slice [16 rows x 512] chunked [4][16][132]
    for (int idx = tid; idx < 2048; idx += 256) {
        int kc = idx >> 9;
        int n  = (idx >> 5) & 15;
        int q  = idx & 31;
        int R  = ((n >> 2) << 9) + j0 + (n & 3);   // gate*512 + j
        float4 v = *(const float4*)(Wh + (size_t)R * HDIM + kc * 128 + q * 4);
        float* d = &WHp[kc * 2112 + n * 132 + q * 4];
        d[0] = v.x; d[1] = v.y; d[2] = v.z; d[3] = v.w;
    }

    // c state in registers (threads 0..127 own (batch ab, col j0+aj))
    int ab = tid >> 2, aj = tid & 3;
    float c_reg = 0.f;
    if (tid < 128) c_reg = c0[ab * HDIM + j0 + aj];
    __syncthreads();

    const float* hsrc = h0;

    for (int t = 0; t < T_STEPS; t++) {
        // wait for previous step's h chunks (all threads poll; acquire orders
        // the subsequent cp.async source reads after visibility)
        if (t > 0) {
            unsigned p   = (unsigned)(t - 1) & 1u;
            unsigned tgt = 32u * ((((unsigned)(t - 1)) >> 1) + 1u);
#pragma unroll
            for (int kc = 0; kc < 4; kc++)
                while (ld_acquire(&g_cnt[p][kc]) < tgt) { }
        }

        // prefetch full h (4 chunks, 4 commit groups; 4 cp.async16/thread each)
#pragma unroll
        for (int kc = 0; kc < 4; kc++) {
#pragma unroll
            for (int r = 0; r < 4; r++) {
                int idx = tid + r * 256;
                int b = idx >> 5, q = idx & 31;
                uint32_t sa = smem_base + (HS_OFF + kc * 4224 + b * 132 + q * 4) * 4;
                cp_async16(sa, hsrc + b * HDIM + kc * 128 + q * 4);
            }
            cp_commit();
        }

        // prefetch this thread's Gx values (hidden under compute)
        float gxv[4];
        if (tid < 128) {
            const float* gx = g_Gx + (size_t)t * BATCH * GDIM + ab * GDIM + j0 + aj;
#pragma unroll
            for (int g = 0; g < 4; g++) gxv[g] = __ldg(gx + g * HDIM);
        }

        ULL acc2[32];   // [p4][n] flattened: p4*8+n ; f32x2 = batches (2p4, 2p4+1)
#pragma unroll
        for (int m = 0; m < 32; m++) acc2[m] = 0ull;

#pragma unroll
        for (int kc = 0; kc < 4; kc++) {
            if (kc == 0) cp_wait<3>();
            else if (kc == 1) cp_wait<2>();
            else if (kc == 2) cp_wait<1>();
            else cp_wait<0>();
            __syncthreads();

            const float* hb = sm + HS_OFF + kc * 4224;
            const float* wb = WHp + kc * 2112;
#pragma unroll
            for (int m = 0; m < 4; m++) {
                int k = ks + (m << 5);
                ULL w2[8];
#pragma unroll
                for (int n = 0; n < 8; n++)
                    w2[n] = splat2(wb[(tn * 8 + n) * 132 + k]);
                ULL h2[4];
#pragma unroll
                for (int p = 0; p < 4; p++)
                    h2[p] = pack2(hb[(tb * 8 + 2 * p) * 132 + k],
                                  hb[(tb * 8 + 2 * p + 1) * 132 + k]);
#pragma unroll
                for (int p = 0; p < 4; p++)
#pragma unroll
                    for (int n = 0; n < 8; n++)
                        ffma2(acc2[p * 8 + n], h2[p], w2[n]);
            }
        }

        // K-split reduction over 32 lanes: value-halving butterfly.
        // After 5 rounds lane ks owns the fully-summed pair for index m=ks.
#pragma unroll
        for (int r = 0; r < 5; r++) {
            const int d    = 16 >> r;
            const int half = 16 >> r;   // cnt/2 where cnt = 32>>r
            const bool hi  = (ks & d) != 0;
#pragma unroll
            for (int j = 0; j < 16; j++) {
                if (j < half) {
                    ULL send = hi ? acc2[j] : acc2[j + half];
                    ULL keep = hi ? acc2[j + half] : acc2[j];
                    ULL recv = __shfl_xor_sync(0xffffffffu, send, d);
                    acc2[j] = fadd2(keep, recv);
                }
            }
        }
        // lane ks: p4 = ks>>3, n = ks&7 -> batches (tb*8+2p4, +1), gatecol tn*8+n
        {
            int b0 = tb * 8 + 2 * (ks >> 3);
            int gc = tn * 8 + (ks & 7);
            *(ULL*)&EXp[gc * 34 + b0] = acc2[0];
        }
        __syncthreads();

        // activations for (batch ab, col j0+aj) on threads 0..127
        if (tid < 128) {
            float g4[4];
#pragma unroll
            for (int g = 0; g < 4; g++)
                g4[g] = EXp[(g * 4 + aj) * 34 + ab] + gxv[g];
            float ig = 1.f / (1.f + __expf(-g4[0]));
            float fg = 1.f / (1.f + __expf(-g4[1]));
            float gg = tanhf(g4[2]);
            float og = 1.f / (1.f + __expf(-g4[3]));
            c_reg = fg * c_reg + ig * gg;
            float hn = og * tanhf(c_reg);
            int off = ab * HDIM + j0 + aj;
            out [(size_t)t * BATCH * HDIM + off] = hn;
            allh[(size_t)t * BATCH * HDIM + off] = hn;
            if (t == T_STEPS - 1) {
                hT[off] = hn;
                cT[off] = c_reg;
            }
        }

        // release: make h(t) visible, then signal our chunk counter
        __threadfence();
        __syncthreads();
        if (tid == 0) atomicAdd(&g_cnt[t & 1][kc_own], 1u);

        hsrc = out + (size_t)t * BATCH * HDIM;
    }

    // terminal barrier + counter reset (replay safety)
    __syncthreads();
    if (tid == 0) {
        __threadfence();
        unsigned gen = g_gen;
        if (atomicAdd(&g_count, 1) == (unsigned)(gridDim.x - 1)) {
            atomicExch(&g_count, 0);
            __threadfence();
            g_gen = gen + 1;
        } else {
            while (g_gen == gen) { }
        }
    }
    __syncthreads();
    if (blockIdx.x == 0 && tid < 8) ((unsigned*)g_cnt)[tid] = 0;
}

// ---------------------------------------------------------------------------
// Inputs (metadata order): x[T,B,I], h0[1,B,H], c0[1,B,H], Wx[4H,I], Wh[4H,H], b[4H]
// Output: concat(output[T,B,H], h_T[1,B,H], c_T[1,B,H], all_hidden[T,B,H])
// ---------------------------------------------------------------------------
extern "C" void kernel_launch(void* const* d_in, const int* in_sizes, int n_in,
                              void* d_out, int out_size)
{
    const float* x    = (const float*)d_in[0];
    const float* h0   = (const float*)d_in[1];
    const float* c0   = (const float*)d_in[2];
    const float* Wx   = (const float*)d_in[3];
    const float* Wh   = (const float*)d_in[4];
    const float* bias = (const float*)d_in[5];

    float* out  = (float*)d_out;
    float* hT   = out + (size_t)T_STEPS * BATCH * HDIM;
    float* cT   = hT + BATCH * HDIM;
    float* allh = cT + BATCH * HDIM;

    // Phase 1: input projection for all timesteps (one node)
    dim3 ggrid(GDIM / 128, (T_STEPS * BATCH) / 128);
    gemm_xw<<<ggrid, 256>>>(x, Wx, bias);

    // Phase 2: entire recurrence in one persistent kernel (one node)
    cudaFuncSetAttribute(lstm_persist,
                         cudaFuncAttributeMaxDynamicSharedMemorySize,
                         SMEM_FLOATS * (int)sizeof(float));
    lstm_persist<<<NBLK, 256, SMEM_FLOATS * sizeof(float)>>>(
        h0, c0, Wh, out, allh, hT, cT);
}

// round 4
// speedup vs baseline: 1.3777x; 1.1728x over previous
#include <cuda_runtime.h>
#include <math.h>
#include <stdint.h>

// Problem constants (T=1024, B=32, I=512, H=512)
#define T_STEPS 1024
#define BATCH   32
#define IDIM    512
#define HDIM    512
#define GDIM    2048   // 4*H, torch gate order (i, f, g, o)
#define NBLK    128    // persistent blocks (<= 148 SMs, co-resident)

typedef unsigned long long ULL;

// Scratch: precomputed input projection Gx[t][b][4H] = x_t @ Wx^T + b  (256 MB)
__device__ float g_Gx[(size_t)T_STEPS * BATCH * GDIM];

// Aggregated producer counter, double-buffered by step parity. Monotonic within
// a launch; reset to 0 at launch end (behind the terminal grid barrier).
__device__ unsigned g_cnt2[2];

// Terminal grid barrier state (replay-safe: count returns to 0, gen monotonic)
__device__ unsigned g_count = 0;
__device__ volatile unsigned g_gen = 0;

// ---------------------------------------------------------------------------
// f32x2 packed-math helpers (sm_100+; ptxas never emits these from C++)
// ---------------------------------------------------------------------------
__device__ __forceinline__ void ffma2(ULL& acc, ULL a, ULL b) {
    asm("fma.rn.f32x2 %0, %1, %2, %0;" : "+l"(acc) : "l"(a), "l"(b));
}
__device__ __forceinline__ ULL fadd2(ULL a, ULL b) {
    ULL r; asm("add.rn.f32x2 %0, %1, %2;" : "=l"(r) : "l"(a), "l"(b)); return r;
}
__device__ __forceinline__ ULL pack2(float lo, float hi) {
    ULL r; asm("mov.b64 %0, {%1, %2};" : "=l"(r) : "f"(lo), "f"(hi)); return r;
}
__device__ __forceinline__ ULL splat2(float x) {
    ULL r; asm("mov.b64 %0, {%1, %1};" : "=l"(r) : "f"(x)); return r;
}
__device__ __forceinline__ void unpack2(ULL v, float& lo, float& hi) {
    asm("mov.b64 {%0, %1}, %2;" : "=f"(lo), "=f"(hi) : "l"(v));
}

// ---------------------------------------------------------------------------
// cp.async helpers (.cg = L1-bypass: gives cross-SM h coherence via L2)
// ---------------------------------------------------------------------------
__device__ __forceinline__ void cp_async16(uint32_t saddr, const void* gptr) {
    asm volatile("cp.async.cg.shared.global [%0], [%1], 16;\n"
                 :: "r"(saddr), "l"(gptr));
}
__device__ __forceinline__ void cp_commit() {
    asm volatile("cp.async.commit_group;\n");
}
template<int N> __device__ __forceinline__ void cp_wait() {
    asm volatile("cp.async.wait_group %0;\n" :: "n"(N));
}

__device__ __forceinline__ unsigned ld_acquire(const unsigned* p) {
    unsigned v;
    asm volatile("ld.acquire.gpu.global.u32 %0, [%1];" : "=r"(v) : "l"(p) : "memory");
    return v;
}

// ---------------------------------------------------------------------------
// Phase 1: Gx = X @ Wx^T + b.  128x128 tile, 256 threads, 8x8/thread,
// double-buffered smem, f32x2 accumulation.  M=32768, N=2048, K=512.
// ---------------------------------------------------------------------------
__global__ __launch_bounds__(256, 2) void gemm_xw(
    const float* __restrict__ A,
    const float* __restrict__ W,
    const float* __restrict__ bias)
{
    const int K = IDIM, N = GDIM;
    __shared__ float As[2][8][128];
    __shared__ float Bs[2][8][128];

    int tid  = threadIdx.x;
    int tx   = tid & 15;
    int ty   = tid >> 4;
    int lrow = tid >> 1;
    int lk4  = (tid & 1) << 2;

    const float* Ag = A + (size_t)(blockIdx.y * 128 + lrow) * K + lk4;
    const float* Wg = W + (size_t)(blockIdx.x * 128 + lrow) * K + lk4;

    ULL acc2[4][8];
#pragma unroll
    for (int p = 0; p < 4; p++)
#pragma unroll
        for (int j = 0; j < 8; j++) acc2[p][j] = 0ull;

    float4 a = *(const float4*)(Ag);
    float4 w = *(const float4*)(Wg);
    As[0][lk4 + 0][lrow] = a.x; As[0][lk4 + 1][lrow] = a.y;
    As[0][lk4 + 2][lrow] = a.z; As[0][lk4 + 3][lrow] = a.w;
    Bs[0][lk4 + 0][lrow] = w.x; Bs[0][lk4 + 1][lrow] = w.y;
    Bs[0][lk4 + 2][lrow] = w.z; Bs[0][lk4 + 3][lrow] = w.w;
    __syncthreads();

    int buf = 0;
    for (int k0 = 0; k0 < K; k0 += 8) {
        if (k0 + 8 < K) {
            a = *(const float4*)(Ag + k0 + 8);
            w = *(const float4*)(Wg + k0 + 8);
        }
#pragma unroll
        for (int k = 0; k < 8; k++) {
            float4 a0 = *(const float4*)&As[buf][k][ty * 4];
            float4 a1 = *(const float4*)&As[buf][k][ty * 4 + 64];
            float4 b0 = *(const float4*)&Bs[buf][k][tx * 4];
            float4 b1 = *(const float4*)&Bs[buf][k][tx * 4 + 64];
            ULL ap[4];
            ap[0] = pack2(a0.x, a0.y); ap[1] = pack2(a0.z, a0.w);
            ap[2] = pack2(a1.x, a1.y); ap[3] = pack2(a1.z, a1.w);
            float brf[8] = {b0.x, b0.y, b0.z, b0.w, b1.x, b1.y, b1.z, b1.w};
            ULL bp[8];
#pragma unroll
            for (int j = 0; j < 8; j++) bp[j] = splat2(brf[j]);
#pragma unroll
            for (int p = 0; p < 4; p++)
#pragma unroll
                for (int j = 0; j < 8; j++)
                    ffma2(acc2[p][j], ap[p], bp[j]);
        }
        if (k0 + 8 < K) {
            int nb = buf ^ 1;
            As[nb][lk4 + 0][lrow] = a.x; As[nb][lk4 + 1][lrow] = a.y;
            As[nb][lk4 + 2][lrow] = a.z; As[nb][lk4 + 3][lrow] = a.w;
            Bs[nb][lk4 + 0][lrow] = w.x; Bs[nb][lk4 + 1][lrow] = w.y;
            Bs[nb][lk4 + 2][lrow] = w.z; Bs[nb][lk4 + 3][lrow] = w.w;
            __syncthreads();
            buf = nb;
        }
    }

#pragma unroll
    for (int i = 0; i < 8; i++) {
        int r = blockIdx.y * 128 + ((i < 4) ? (ty * 4 + i) : (64 + ty * 4 + (i - 4)));
#pragma unroll
        for (int jh = 0; jh < 2; jh++) {
            int c0 = blockIdx.x * 128 + ((jh == 0) ? (tx * 4) : (64 + tx * 4));
            float v[4];
#pragma unroll
            for (int jj = 0; jj < 4; jj++) {
                float lo, hi;
                unpack2(acc2[i >> 1][jh * 4 + jj], lo, hi);
                v[jj] = (i & 1) ? hi : lo;
            }
            float4 o;
            o.x = v[0] + bias[c0 + 0];
            o.y = v[1] + bias[c0 + 1];
            o.z = v[2] + bias[c0 + 2];
            o.w = v[3] + bias[c0 + 3];
            *(float4*)&g_Gx[(size_t)r * N + c0] = o;
        }
    }
}

// ---------------------------------------------------------------------------
// Persistent LSTM recurrence.
// 128 blocks x 256 threads. Block bx owns h-columns j0..j0+3 (16 Wh rows).
// Thread map: ks = lane (K-split 32), tn = (tid>>5)&1 (8 of 16 gate cols),
// tb = tid>>6 (8 of 32 batches). f32x2 accumulators pair adjacent batches.
// smem (floats):
//   WH [4][16][132]  @0      (8448)   Wh slice, cached once
//   HS [4][32][132]  @8448   (16896)  full h staging (one step)
//   EX [16][34]      @25344  (544)    gate-sum exchange
// ---------------------------------------------------------------------------
#define WH_OFF 0
#define HS_OFF 8448
#define EX_OFF 25344
#define SMEM_FLOATS 25888

__global__ __launch_bounds__(256, 1) void lstm_persist(
    const float* __restrict__ h0,
    const float* __restrict__ c0,
    const float* __restrict__ Wh,
    float* __restrict__ out,    // [T][32][512]
    float* __restrict__ allh,   // [T][32][512]
    float* __restrict__ hT,     // [32][512]
    float* __restrict__ cT)     // [32][512]
{
    extern __shared__ float sm[];
    float* WHp = sm + WH_OFF;
    float* EXp = sm + EX_OFF;

    const int tid = threadIdx.x;
    const int j0  = blockIdx.x * 4;
    const int ks  = tid & 31;          // lane == K-split index
    const int tn  = (tid >> 5) & 1;    // gate-col half
    const int tb  = tid >> 6;          // batch quarter

    uint32_t smem_base = (uint32_t)__cvta_generic_to_shared(sm);

    // one-time: cache Wh slice [16 rows x 512] chunked [4][16][132]
    for (int idx = tid; idx < 2048; idx += 256) {
        int kc = idx >> 9;
        int n  = (idx >> 5) & 15;
        int q  = idx & 31;
        int R  = ((n >> 2) << 9) + j0 + (n & 3);   // gate*512 + j
        float4 v = *(const float4*)(Wh + (size_t)R * HDIM + kc * 128 + q * 4);
        float* d = &WHp[kc * 2112 + n * 132 + q * 4];
        d[0] = v.x; d[1] = v.y; d[2] = v.z; d[3] = v.w;
    }

    // c state in registers (threads 0..127 own (batch ab, col j0+aj))
    int ab = tid >> 2, aj = tid & 3;
    float c_reg = 0.f;
    if (tid < 128) c_reg = c0[ab * HDIM + j0 + aj];
    __syncthreads();

    const float* hsrc = h0;

    for (int t = 0; t < T_STEPS; t++) {
        // prefetch this thread's Gx values (phase-1 output: always ready;
        // issued BEFORE the poll so its latency hides under the wait)
        float gxv[4];
        if (tid < 128) {
            const float* gx = g_Gx + (size_t)t * BATCH * GDIM + ab * GDIM + j0 + aj;
#pragma unroll
            for (int g = 0; g < 4; g++) gxv[g] = __ldg(gx + g * HDIM);
        }

        // wait for ALL producers of h(t-1): leader polls ONE aggregated
        // counter, barrier broadcasts the acquire to the block.
        if (t > 0) {
            if (tid == 0) {
                unsigned p   = (unsigned)(t - 1) & 1u;
                unsigned tgt = 128u * ((((unsigned)(t - 1)) >> 1) + 1u);
                while (ld_acquire(&g_cnt2[p]) < tgt) { }
            }
            __syncthreads();
        }

        // prefetch full h (4 chunks, 4 commit groups; 4 cp.async16/thread each)
#pragma unroll
        for (int kc = 0; kc < 4; kc++) {
#pragma unroll
            for (int r = 0; r < 4; r++) {
                int idx = tid + r * 256;
                int b = idx >> 5, q = idx & 31;
                uint32_t sa = smem_base + (HS_OFF + kc * 4224 + b * 132 + q * 4) * 4;
                cp_async16(sa, hsrc + b * HDIM + kc * 128 + q * 4);
            }
            cp_commit();
        }

        ULL acc2[32];   // [p4][n] flattened: p4*8+n ; f32x2 = batches (2p4, 2p4+1)
#pragma unroll
        for (int m = 0; m < 32; m++) acc2[m] = 0ull;

#pragma unroll
        for (int kc = 0; kc < 4; kc++) {
            if (kc == 0) cp_wait<3>();
            else if (kc == 1) cp_wait<2>();
            else if (kc == 2) cp_wait<1>();
            else cp_wait<0>();
            __syncthreads();

            const float* hb = sm + HS_OFF + kc * 4224;
            const float* wb = WHp + kc * 2112;
#pragma unroll
            for (int m = 0; m < 4; m++) {
                int k = ks + (m << 5);
                ULL w2[8];
#pragma unroll
                for (int n = 0; n < 8; n++)
                    w2[n] = splat2(wb[(tn * 8 + n) * 132 + k]);
                ULL h2[4];
#pragma unroll
                for (int p = 0; p < 4; p++)
                    h2[p] = pack2(hb[(tb * 8 + 2 * p) * 132 + k],
                                  hb[(tb * 8 + 2 * p + 1) * 132 + k]);
#pragma unroll
                for (int p = 0; p < 4; p++)
#pragma unroll
                    for (int n = 0; n < 8; n++)
                        ffma2(acc2[p * 8 + n], h2[p], w2[n]);
            }
        }

        // K-split reduction over 32 lanes: value-halving butterfly.
#pragma unroll
        for (int r = 0; r < 5; r++) {
            const int d    = 16 >> r;
            const int half = 16 >> r;
#pragma unroll
            for (int j = 0; j < 16; j++) {
                if (j < half) {
                    const bool hi = (ks & d) != 0;
                    ULL send = hi ? acc2[j] : acc2[j + half];
                    ULL keep = hi ? acc2[j + half] : acc2[j];
                    ULL recv = __shfl_xor_sync(0xffffffffu, send, d);
                    acc2[j] = fadd2(keep, recv);
                }
            }
        }
        // lane ks owns pair for p4 = ks>>3, n = ks&7
        {
            int b0 = tb * 8 + 2 * (ks >> 3);
            int gc = tn * 8 + (ks & 7);
            *(ULL*)&EXp[gc * 34 + b0] = acc2[0];
        }
        __syncthreads();

        // activations for (batch ab, col j0+aj) on threads 0..127
        if (tid < 128) {
            float g4[4];
#pragma unroll
            for (int g = 0; g < 4; g++)
                g4[g] = EXp[(g * 4 + aj) * 34 + ab] + gxv[g];
            float ig = 1.f / (1.f + __expf(-g4[0]));
            float fg = 1.f / (1.f + __expf(-g4[1]));
            float gg = tanhf(g4[2]);
            float og = 1.f / (1.f + __expf(-g4[3]));
            c_reg = fg * c_reg + ig * gg;
            float hn = og * tanhf(c_reg);
            int off = ab * HDIM + j0 + aj;
            out [(size_t)t * BATCH * HDIM + off] = hn;
            allh[(size_t)t * BATCH * HDIM + off] = hn;
            if (t == T_STEPS - 1) {
                hT[off] = hn;
                cT[off] = c_reg;
            }
        }

        // release: make h(t) visible, then signal the aggregated counter
        __threadfence();
        __syncthreads();
        if (tid == 0) atomicAdd(&g_cnt2[t & 1], 1u);

        hsrc = out + (size_t)t * BATCH * HDIM;
    }

    // terminal barrier + counter reset (replay safety)
    __syncthreads();
    if (tid == 0) {
        __threadfence();
        unsigned gen = g_gen;
        if (atomicAdd(&g_count, 1) == (unsigned)(gridDim.x - 1)) {
            atomicExch(&g_count, 0);
            __threadfence();
            g_gen = gen + 1;
        } else {
            while (g_gen == gen) { }
        }
    }
    __syncthreads();
    if (blockIdx.x == 0 && tid < 2) g_cnt2[tid] = 0;
}

// ---------------------------------------------------------------------------
// Inputs (metadata order): x[T,B,I], h0[1,B,H], c0[1,B,H], Wx[4H,I], Wh[4H,H], b[4H]
// Output: concat(output[T,B,H], h_T[1,B,H], c_T[1,B,H], all_hidden[T,B,H])
// ---------------------------------------------------------------------------
extern "C" void kernel_launch(void* const* d_in, const int* in_sizes, int n_in,
                              void* d_out, int out_size)
{
    const float* x    = (const float*)d_in[0];
    const float* h0   = (const float*)d_in[1];
    const float* c0   = (const float*)d_in[2];
    const float* Wx   = (const float*)d_in[3];
    const float* Wh   = (const float*)d_in[4];
    const float* bias = (const float*)d_in[5];

    float* out  = (float*)d_out;
    float* hT   = out + (size_t)T_STEPS * BATCH * HDIM;
    float* cT   = hT + BATCH * HDIM;
    float* allh = cT + BATCH * HDIM;

    // Phase 1: input projection for all timesteps (one node)
    dim3 ggrid(GDIM / 128, (T_STEPS * BATCH) / 128);
    gemm_xw<<<ggrid, 256>>>(x, Wx, bias);

    // Phase 2: entire recurrence in one persistent kernel (one node)
    cudaFuncSetAttribute(lstm_persist,
                         cudaFuncAttributeMaxDynamicSharedMemorySize,
                         SMEM_FLOATS * (int)sizeof(float));
    lstm_persist<<<NBLK, 256, SMEM_FLOATS * sizeof(float)>>>(
        h0, c0, Wh, out, allh, hT, cT);
}

// round 5
// speedup vs baseline: 1.4991x; 1.0882x over previous
#include <cuda_runtime.h>
#include <math.h>
#include <stdint.h>

// Problem constants (T=1024, B=32, I=512, H=512)
#define T_STEPS 1024
#define BATCH   32
#define IDIM    512
#define HDIM    512
#define GDIM    2048   // 4*H, torch gate order (i, f, g, o)
#define NBLK    128    // persistent blocks (co-resident)

typedef unsigned long long ULL;

// Scratch: precomputed input projection Gx[t][b][4H] (256 MB)
__device__ float g_Gx[(size_t)T_STEPS * BATCH * GDIM];

// Transposed h chain: g_hT[t][k][b], t = 0..T (index t holds h(t-1); 0 = h0).
// Addresses are never reused within a launch -> cp.async.ca (L1) is safe.
__device__ float g_hT[(size_t)(T_STEPS + 1) * HDIM * BATCH];

// Aggregated producer counter, double-buffered by step parity (monotonic,
// reset behind the terminal barrier).
__device__ unsigned g_cnt2[2];

// Terminal grid barrier state
__device__ unsigned g_count = 0;
__device__ volatile unsigned g_gen = 0;

// ---------------------------------------------------------------------------
// f32x2 packed-math helpers
// ---------------------------------------------------------------------------
__device__ __forceinline__ void ffma2(ULL& acc, ULL a, ULL b) {
    asm("fma.rn.f32x2 %0, %1, %2, %0;" : "+l"(acc) : "l"(a), "l"(b));
}
__device__ __forceinline__ ULL fadd2(ULL a, ULL b) {
    ULL r; asm("add.rn.f32x2 %0, %1, %2;" : "=l"(r) : "l"(a), "l"(b)); return r;
}
__device__ __forceinline__ ULL pack2(float lo, float hi) {
    ULL r; asm("mov.b64 %0, {%1, %2};" : "=l"(r) : "f"(lo), "f"(hi)); return r;
}
__device__ __forceinline__ ULL splat2(float x) {
    ULL r; asm("mov.b64 %0, {%1, %1};" : "=l"(r) : "f"(x)); return r;
}
__device__ __forceinline__ void unpack2(ULL v, float& lo, float& hi) {
    asm("mov.b64 {%0, %1}, %2;" : "=f"(lo), "=f"(hi) : "l"(v));
}

// ---------------------------------------------------------------------------
// async-copy / sync helpers
// ---------------------------------------------------------------------------
__device__ __forceinline__ void cp_async16(uint32_t saddr, const void* gptr) {
    asm volatile("cp.async.cg.shared.global [%0], [%1], 16;\n"
                 :: "r"(saddr), "l"(gptr));
}
__device__ __forceinline__ void cp_async8(uint32_t saddr, const void* gptr) {
    asm volatile("cp.async.ca.shared.global [%0], [%1], 8;\n"
                 :: "r"(saddr), "l"(gptr));
}
__device__ __forceinline__ void cp_commit() {
    asm volatile("cp.async.commit_group;\n");
}
template<int N> __device__ __forceinline__ void cp_wait() {
    asm volatile("cp.async.wait_group %0;\n" :: "n"(N));
}
__device__ __forceinline__ unsigned ld_acquire(const unsigned* p) {
    unsigned v;
    asm volatile("ld.acquire.gpu.global.u32 %0, [%1];" : "=r"(v) : "l"(p) : "memory");
    return v;
}
__device__ __forceinline__ void red_release_add(unsigned* p, unsigned v) {
    asm volatile("red.release.gpu.global.add.u32 [%0], %1;" :: "l"(p), "r"(v) : "memory");
}

// ---------------------------------------------------------------------------
// Seed: g_hT[0][k][b] = h0[b][k]
// ---------------------------------------------------------------------------
__global__ void seed_hT(const float* __restrict__ h0)
{
    int i = blockIdx.x * 256 + threadIdx.x;   // 16384
    int b = i >> 9, k = i & 511;
    g_hT[(size_t)k * BATCH + b] = h0[b * HDIM + k];
}

// ---------------------------------------------------------------------------
// Phase 1: Gx = X @ Wx^T + b.  128x128 tile, 256 threads, f32x2, double-buffer.
// ---------------------------------------------------------------------------
__global__ __launch_bounds__(256, 2) void gemm_xw(
    const float* __restrict__ A,
    const float* __restrict__ W,
    const float* __restrict__ bias)
{
    const int K = IDIM, N = GDIM;
    __shared__ float As[2][8][128];
    __shared__ float Bs[2][8][128];

    int tid  = threadIdx.x;
    int tx   = tid & 15;
    int ty   = tid >> 4;
    int lrow = tid >> 1;
    int lk4  = (tid & 1) << 2;

    const float* Ag = A + (size_t)(blockIdx.y * 128 + lrow) * K + lk4;
    const float* Wg = W + (size_t)(blockIdx.x * 128 + lrow) * K + lk4;

    ULL acc2[4][8];
#pragma unroll
    for (int p = 0; p < 4; p++)
#pragma unroll
        for (int j = 0; j < 8; j++) acc2[p][j] = 0ull;

    float4 a = *(const float4*)(Ag);
    float4 w = *(const float4*)(Wg);
    As[0][lk4 + 0][lrow] = a.x; As[0][lk4 + 1][lrow] = a.y;
    As[0][lk4 + 2][lrow] = a.z; As[0][lk4 + 3][lrow] = a.w;
    Bs[0][lk4 + 0][lrow] = w.x; Bs[0][lk4 + 1][lrow] = w.y;
    Bs[0][lk4 + 2][lrow] = w.z; Bs[0][lk4 + 3][lrow] = w.w;
    __syncthreads();

    int buf = 0;
    for (int k0 = 0; k0 < K; k0 += 8) {
        if (k0 + 8 < K) {
            a = *(const float4*)(Ag + k0 + 8);
            w = *(const float4*)(Wg + k0 + 8);
        }
#pragma unroll
        for (int k = 0; k < 8; k++) {
            float4 a0 = *(const float4*)&As[buf][k][ty * 4];
            float4 a1 = *(const float4*)&As[buf][k][ty * 4 + 64];
            float4 b0 = *(const float4*)&Bs[buf][k][tx * 4];
            float4 b1 = *(const float4*)&Bs[buf][k][tx * 4 + 64];
            ULL ap[4];
            ap[0] = pack2(a0.x, a0.y); ap[1] = pack2(a0.z, a0.w);
            ap[2] = pack2(a1.x, a1.y); ap[3] = pack2(a1.z, a1.w);
            float brf[8] = {b0.x, b0.y, b0.z, b0.w, b1.x, b1.y, b1.z, b1.w};
            ULL bp[8];
#pragma unroll
            for (int j = 0; j < 8; j++) bp[j] = splat2(brf[j]);
#pragma unroll
            for (int p = 0; p < 4; p++)
#pragma unroll
                for (int j = 0; j < 8; j++)
                    ffma2(acc2[p][j], ap[p], bp[j]);
        }
        if (k0 + 8 < K) {
            int nb = buf ^ 1;
            As[nb][lk4 + 0][lrow] = a.x; As[nb][lk4 + 1][lrow] = a.y;
            As[nb][lk4 + 2][lrow] = a.z; As[nb][lk4 + 3][lrow] = a.w;
            Bs[nb][lk4 + 0][lrow] = w.x; Bs[nb][lk4 + 1][lrow] = w.y;
            Bs[nb][lk4 + 2][lrow] = w.z; Bs[nb][lk4 + 3][lrow] = w.w;
            __syncthreads();
            buf = nb;
        }
    }

#pragma unroll
    for (int i = 0; i < 8; i++) {
        int r = blockIdx.y * 128 + ((i < 4) ? (ty * 4 + i) : (64 + ty * 4 + (i - 4)));
#pragma unroll
        for (int jh = 0; jh < 2; jh++) {
            int c0 = blockIdx.x * 128 + ((jh == 0) ? (tx * 4) : (64 + tx * 4));
            float v[4];
#pragma unroll
            for (int jj = 0; jj < 4; jj++) {
                float lo, hi;
                unpack2(acc2[i >> 1][jh * 4 + jj], lo, hi);
                v[jj] = (i & 1) ? hi : lo;
            }
            float4 o;
            o.x = v[0] + bias[c0 + 0];
            o.y = v[1] + bias[c0 + 1];
            o.z = v[2] + bias[c0 + 2];
            o.w = v[3] + bias[c0 + 3];
            *(float4*)&g_Gx[(size_t)r * N + c0] = o;
        }
    }
}

// ---------------------------------------------------------------------------
// Persistent LSTM recurrence.
// 128 blocks x 256 threads. Block bx owns h-cols j0..j0+3 (16 gate rows).
// Lane = K-split 32; tn = (tid>>5)&1 (8 of 16 gate rows); tb = tid>>6.
// smem (floats):
//   WT [4][128][17]  @0      (8704)   Wh transposed [k][r], cached once
//   HT [4][128][34]  @8704   (17408)  h transposed [k][b] staging
//   EX [16][34]      @26112  (544)    gate-sum exchange
// ---------------------------------------------------------------------------
#define WT_OFF 0
#define HT_OFF 8704
#define EX_OFF 26112
#define SMEM_FLOATS 26656

__global__ __launch_bounds__(256, 1) void lstm_persist(
    const float* __restrict__ c0,
    const float* __restrict__ Wh,
    float* __restrict__ out,    // [T][32][512]
    float* __restrict__ cT)     // [32][512]
{
    extern __shared__ float sm[];
    float* WTp = sm + WT_OFF;
    float* EXp = sm + EX_OFF;

    const int tid = threadIdx.x;
    const int j0  = blockIdx.x * 4;
    const int ks  = tid & 31;          // lane == K-split index
    const int tn  = (tid >> 5) & 1;    // gate-row half
    const int tb  = tid >> 6;          // batch quarter

    uint32_t smem_base = (uint32_t)__cvta_generic_to_shared(sm);

    // one-time: cache Wh slice transposed: WT[kc][k][r] = Wh[R(r)][kc*128+k]
    for (int idx = tid; idx < 8192; idx += 256) {
        int r  = idx >> 9;            // 0..15 : gate*4 + colj
        int kf = idx & 511;           // 0..511
        int R  = ((r >> 2) << 9) + j0 + (r & 3);
        float v = Wh[(size_t)R * HDIM + kf];
        int kc = kf >> 7, k = kf & 127;
        WTp[kc * 2176 + k * 17 + r] = v;
    }

    // c state in registers (threads 0..127 own (batch ab, col j0+aj))
    int ab = tid >> 2, aj = tid & 3;
    float c_reg = 0.f;
    if (tid < 128) c_reg = c0[ab * HDIM + j0 + aj];
    __syncthreads();

    for (int t = 0; t < T_STEPS; t++) {
        // Gx prefetch (always ready) BEFORE the poll: latency hides under wait
        float gxv[4];
        if (tid < 128) {
            const float* gx = g_Gx + (size_t)t * BATCH * GDIM + ab * GDIM + j0 + aj;
#pragma unroll
            for (int g = 0; g < 4; g++) gxv[g] = __ldg(gx + g * HDIM);
        }

        // wait for all producers of h(t-1): leader polls aggregated counter
        if (t > 0) {
            if (tid == 0) {
                unsigned p   = (unsigned)(t - 1) & 1u;
                unsigned tgt = 128u * ((((unsigned)(t - 1)) >> 1) + 1u);
                while (ld_acquire(&g_cnt2[p]) < tgt) { }
            }
            __syncthreads();
        }

        // stage h(t-1) transposed: g_hT[t][k][b] -> HT[kc][k][34-stride]
        const float* hsrc = g_hT + (size_t)t * HDIM * BATCH;
#pragma unroll
        for (int kc = 0; kc < 4; kc++) {
#pragma unroll
            for (int r = 0; r < 8; r++) {
                int idx = r * 256 + tid;           // 0..2047
                int k = idx >> 4, q = idx & 15;    // q: 8-byte unit in row
                uint32_t sa = smem_base + (HT_OFF + kc * 4352 + k * 34 + q * 2) * 4;
                cp_async8(sa, hsrc + (size_t)(kc * 128 + k) * BATCH + q * 2);
            }
            cp_commit();
        }

        ULL acc2[32];   // [p][n]: batches (tb*8+2p, +1) x gate-row tn*8+n
#pragma unroll
        for (int m = 0; m < 32; m++) acc2[m] = 0ull;

#pragma unroll
        for (int kc = 0; kc < 4; kc++) {
            if (kc == 0) cp_wait<3>();
            else if (kc == 1) cp_wait<2>();
            else if (kc == 2) cp_wait<1>();
            else cp_wait<0>();
            __syncthreads();

            const float* hc = sm + HT_OFF + kc * 4352;
            const float* wc = WTp + kc * 2176;
#pragma unroll
            for (int m = 0; m < 4; m++) {
                int k = ks + (m << 5);
                const float* wb = wc + k * 17 + tn * 8;
                const float* hb = hc + k * 34 + tb * 8;
                ULL h2[4];
#pragma unroll
                for (int p = 0; p < 4; p++)
                    h2[p] = *(const ULL*)&hb[2 * p];          // LDS.64, pre-paired
                ULL w2[8];
#pragma unroll
                for (int n = 0; n < 8; n++) w2[n] = splat2(wb[n]);
#pragma unroll
                for (int p = 0; p < 4; p++)
#pragma unroll
                    for (int n = 0; n < 8; n++)
                        ffma2(acc2[p * 8 + n], h2[p], w2[n]);
            }
        }

        // K-split reduction: value-halving butterfly over 32 lanes
#pragma unroll
        for (int r = 0; r < 5; r++) {
            const int d    = 16 >> r;
            const int half = 16 >> r;
#pragma unroll
            for (int j = 0; j < 16; j++) {
                if (j < half) {
                    const bool hi = (ks & d) != 0;
                    ULL send = hi ? acc2[j] : acc2[j + half];
                    ULL keep = hi ? acc2[j + half] : acc2[j];
                    ULL recv = __shfl_xor_sync(0xffffffffu, send, d);
                    acc2[j] = fadd2(keep, recv);
                }
            }
        }
        {   // lane ks owns pair for p = ks>>3, n = ks&7
            int b0 = tb * 8 + 2 * (ks >> 3);
            int gc = tn * 8 + (ks & 7);
            *(ULL*)&EXp[gc * 34 + b0] = acc2[0];
        }
        __syncthreads();

        // activations on threads 0..127
        if (tid < 128) {
            float g4[4];
#pragma unroll
            for (int g = 0; g < 4; g++)
                g4[g] = EXp[(g * 4 + aj) * 34 + ab] + gxv[g];
            float ig = 1.f / (1.f + __expf(-g4[0]));
            float fg = 1.f / (1.f + __expf(-g4[1]));
            float gg = tanhf(g4[2]);
            float og = 1.f / (1.f + __expf(-g4[3]));
            c_reg = fg * c_reg + ig * gg;
            float hn = og * tanhf(c_reg);
            out[(size_t)t * BATCH * HDIM + ab * HDIM + j0 + aj] = hn;
            g_hT[(size_t)(t + 1) * HDIM * BATCH + (j0 + aj) * BATCH + ab] = hn;
            if (t == T_STEPS - 1) cT[ab * HDIM + j0 + aj] = c_reg;
        }

        // release: CTA barrier orders all stores before tid0's release-red
        __syncthreads();
        if (tid == 0) red_release_add(&g_cnt2[t & 1], 1u);
    }

    // terminal barrier + counter reset (replay safety)
    __syncthreads();
    if (tid == 0) {
        __threadfence();
        unsigned gen = g_gen;
        if (atomicAdd(&g_count, 1) == (unsigned)(gridDim.x - 1)) {
            atomicExch(&g_count, 0);
            __threadfence();
            g_gen = gen + 1;
        } else {
            while (g_gen == gen) { }
        }
    }
    __syncthreads();
    if (blockIdx.x == 0 && tid < 2) g_cnt2[tid] = 0;
}

// ---------------------------------------------------------------------------
// Post-copies: allh = out (16M floats), hT = out[T-1]
// ---------------------------------------------------------------------------
__global__ void copy_allh(const float4* __restrict__ src, float4* __restrict__ dst)
{
    size_t i = (size_t)blockIdx.x * blockDim.x + threadIdx.x;
    size_t n = (size_t)T_STEPS * BATCH * HDIM / 4;
    for (; i < n; i += (size_t)gridDim.x * blockDim.x) dst[i] = src[i];
}
__global__ void copy_hT(const float4* __restrict__ src, float4* __restrict__ dst)
{
    int i = blockIdx.x * blockDim.x + threadIdx.x;
    if (i < BATCH * HDIM / 4) dst[i] = src[i];
}

// ---------------------------------------------------------------------------
// Inputs: x[T,B,I], h0[1,B,H], c0[1,B,H], Wx[4H,I], Wh[4H,H], b[4H]
// Output: concat(output[T,B,H], h_T[1,B,H], c_T[1,B,H], all_hidden[T,B,H])
// ---------------------------------------------------------------------------
extern "C" void kernel_launch(void* const* d_in, const int* in_sizes, int n_in,
                              void* d_out, int out_size)
{
    const float* x    = (const float*)d_in[0];
    const float* h0   = (const float*)d_in[1];
    const float* c0   = (const float*)d_in[2];
    const float* Wx   = (const float*)d_in[3];
    const float* Wh   = (const float*)d_in[4];
    const float* bias = (const float*)d_in[5];

    float* out  = (float*)d_out;
    float* hT   = out + (size_t)T_STEPS * BATCH * HDIM;
    float* cT   = hT + BATCH * HDIM;
    float* allh = cT + BATCH * HDIM;

    seed_hT<<<64, 256>>>(h0);

    dim3 ggrid(GDIM / 128, (T_STEPS * BATCH) / 128);
    gemm_xw<<<ggrid, 256>>>(x, Wx, bias);

    cudaFuncSetAttribute(lstm_persist,
                         cudaFuncAttributeMaxDynamicSharedMemorySize,
                         SMEM_FLOATS * (int)sizeof(float));
    lstm_persist<<<NBLK, 256, SMEM_FLOATS * sizeof(float)>>>(c0, Wh, out, cT);

    copy_allh<<<512, 256>>>((const float4*)out, (float4*)allh);
    copy_hT<<<16, 256>>>(
        (const float4*)(out + (size_t)(T_STEPS - 1) * BATCH * HDIM), (float4*)hT);
}